// round 11
// baseline (speedup 1.0000x reference)
#include <cuda_runtime.h>
#include <cuda_bf16.h>
#include <cstddef>
#include <cstdint>

#define D 128
#define MAX_NODES 50000
#define MAX_EDGES 800000

typedef unsigned int u32;

// Static device scratch (no allocations allowed).
__device__ float g_h[(size_t)MAX_NODES * D];     // layer-0 output
__device__ int   g_degi[MAX_NODES];
__device__ int   g_off[MAX_NODES];
__device__ int   g_cur[MAX_NODES];
__device__ int   g_ssrc[MAX_EDGES];
__device__ int   g_part[64];
__device__ int   g_tile_ctr[2];                  // work-stealing counters (per layer)
// Pre-split packed weights: [layer][plane hi/lo][kp][n], u32 = bf16x2(k=2kp,k=2kp+1).
__device__ u32 g_Bp[2][2][128][128];

// ---------------------------------------------------------------------------
// Weight conversion + zero g_degi + zero tile counters.
// grid = 256 (layer*128 + kp), block = 128 (n).
// ---------------------------------------------------------------------------
__global__ void convert_w_zero_kernel(const float* __restrict__ W0l,
                                      const float* __restrict__ W0r,
                                      const float* __restrict__ W1l,
                                      const float* __restrict__ W1r,
                                      int M) {
    int kp = blockIdx.x & 127;
    int layer = blockIdx.x >> 7;
    int n = threadIdx.x;
    int k0 = 2 * kp;
    const float* W = layer ? (k0 < D ? W1l : W1r) : (k0 < D ? W0l : W0r);
    float v0 = W[(size_t)(k0 & (D - 1)) * D + n];
    float v1 = W[(size_t)((k0 + 1) & (D - 1)) * D + n];
    __nv_bfloat162 h2 = __floats2bfloat162_rn(v0, v1);
    float hx = __bfloat162float(__low2bfloat16(h2));
    float hy = __bfloat162float(__high2bfloat16(h2));
    __nv_bfloat162 l2 = __floats2bfloat162_rn(v0 - hx, v1 - hy);
    g_Bp[layer][0][kp][n] = *reinterpret_cast<u32*>(&h2);
    g_Bp[layer][1][kp][n] = *reinterpret_cast<u32*>(&l2);

    int idx = blockIdx.x * 128 + n;          // 32768 threads, 2 strides cover 50k
    if (idx < M) g_degi[idx] = 0;
    idx += 32768;
    if (idx < M) g_degi[idx] = 0;
    if (blockIdx.x == 0 && n < 2) g_tile_ctr[n] = 0;
}

__global__ void count_deg_kernel(const int* __restrict__ dst, int E) {
    int i = (blockIdx.x * blockDim.x + threadIdx.x) * 4;
    if (i + 4 <= E) {
        int4 d = *reinterpret_cast<const int4*>(dst + i);
        atomicAdd(&g_degi[d.x], 1);
        atomicAdd(&g_degi[d.y], 1);
        atomicAdd(&g_degi[d.z], 1);
        atomicAdd(&g_degi[d.w], 1);
    } else {
        for (; i < E; ++i) atomicAdd(&g_degi[dst[i]], 1);
    }
}

#define SCAN_BLK 1024
__global__ void scan_part_kernel(int n) {
    __shared__ int red[SCAN_BLK];
    int tid = threadIdx.x;
    int i = blockIdx.x * SCAN_BLK + tid;
    red[tid] = (i < n) ? g_degi[i] : 0;
    __syncthreads();
#pragma unroll
    for (int ofs = SCAN_BLK / 2; ofs > 0; ofs >>= 1) {
        if (tid < ofs) red[tid] += red[tid + ofs];
        __syncthreads();
    }
    if (tid == 0) g_part[blockIdx.x] = red[0];
}

// Block scan + serial base accumulation (49 adds per block << launch latency).
__global__ void scan_write_kernel(int n) {
    __shared__ int s[SCAN_BLK];
    __shared__ int sbase;
    int tid = threadIdx.x;
    int i = blockIdx.x * SCAN_BLK + tid;
    int v = (i < n) ? g_degi[i] : 0;
    s[tid] = v;
    if (tid == 0) {
        int run = 0;
        for (int b = 0; b < blockIdx.x; ++b) run += g_part[b];
        sbase = run;
    }
    __syncthreads();
    for (int ofs = 1; ofs < SCAN_BLK; ofs <<= 1) {
        int t = (tid >= ofs) ? s[tid - ofs] : 0;
        __syncthreads();
        s[tid] += t;
        __syncthreads();
    }
    int excl = s[tid] - v + sbase;
    if (i < n) { g_off[i] = excl; g_cur[i] = excl; }
}

__global__ void fill_csr_kernel(const int* __restrict__ src,
                                const int* __restrict__ dst, int E) {
    int i = (blockIdx.x * blockDim.x + threadIdx.x) * 4;
    if (i + 4 <= E) {
        int4 d = *reinterpret_cast<const int4*>(dst + i);
        int4 s = *reinterpret_cast<const int4*>(src + i);
        g_ssrc[atomicAdd(&g_cur[d.x], 1)] = s.x;
        g_ssrc[atomicAdd(&g_cur[d.y], 1)] = s.y;
        g_ssrc[atomicAdd(&g_cur[d.z], 1)] = s.z;
        g_ssrc[atomicAdd(&g_cur[d.w], 1)] = s.w;
    } else {
        for (; i < E; ++i) g_ssrc[atomicAdd(&g_cur[dst[i]], 1)] = src[i];
    }
}

// ---------------------------------------------------------------------------
// Persistent fused gather + SAGE GEMM (3xBF16 mma.sync.m16n8k16), BM=64xBN=128
// tiles pulled via work-stealing counter (balances degree-variance + wave tail).
//   Phase 0: A = mean-gather of H over CSR neighbors (all warps gather).
//   Phase 1: A = H rows (skip path).
//   out = A0@Wl + A1@Wr + mask(deg>0).*bias (+ReLU).
// ---------------------------------------------------------------------------
#define MMA_BF16(c, a, b)                                                      \
    asm volatile(                                                              \
        "mma.sync.aligned.m16n8k16.row.col.f32.bf16.bf16.f32 "                 \
        "{%0,%1,%2,%3},{%4,%5,%6,%7},{%8,%9},{%0,%1,%2,%3};"                   \
        : "+f"((c)[0]), "+f"((c)[1]), "+f"((c)[2]), "+f"((c)[3])               \
        : "r"((a)[0]), "r"((a)[1]), "r"((a)[2]), "r"((a)[3]),                  \
          "r"((b)[0]), "r"((b)[1]))

#define AFS 68          // full-K A stride: 64 packed words + 4 pad
#define BS_STRIDE 136   // B chunk stride: 128 packed cols + 8 pad
#define SMEM_WORDS (2 * 64 * AFS + 2 * 16 * BS_STRIDE)
#define SMEM_BYTES (SMEM_WORDS * 4)

__device__ __forceinline__ void split2(float x, float y, u32& hi, u32& lo) {
    __nv_bfloat162 h2 = __floats2bfloat162_rn(x, y);
    float hx = __bfloat162float(__low2bfloat16(h2));
    float hy = __bfloat162float(__high2bfloat16(h2));
    __nv_bfloat162 l2 = __floats2bfloat162_rn(x - hx, y - hy);
    hi = *reinterpret_cast<u32*>(&h2);
    lo = *reinterpret_cast<u32*>(&l2);
}

template <bool RELU>
__global__ void __launch_bounds__(256, 3)
sage_fused_kernel(const float* __restrict__ H,
                  const u32* __restrict__ Bhi, const u32* __restrict__ Blo,
                  const float* __restrict__ bias, float* __restrict__ out,
                  int M, int ntiles, int layer) {
    extern __shared__ u32 sm[];
    u32* As_hi = sm;                             // 64 * AFS
    u32* As_lo = sm + 64 * AFS;
    u32* Bs_hi = sm + 2 * 64 * AFS;              // 16 * BS_STRIDE
    u32* Bs_lo = sm + 2 * 64 * AFS + 16 * BS_STRIDE;
    __shared__ int s_tile;

    const int tid = threadIdx.x;
    const int warp = tid >> 5;
    const int lane = tid & 31;
    const int gid = lane >> 2;
    const int tig = lane & 3;
    const int wm = (warp >> 2) * 32;
    const int wn = (warp & 3) * 32;

    const int bkp = tid >> 4;            // B staging: packed-k row 0..15
    const int bcn = (tid & 15) * 8;      //           8 cols per thread

    for (;;) {
        if (tid == 0) s_tile = atomicAdd(&g_tile_ctr[layer], 1);
        __syncthreads();     // publishes s_tile; also fences prior tile's As reads
        const int tile = s_tile;
        if (tile >= ntiles) return;
        const int block_row = tile * 64;

        // ---- gather phase: warp w produces A rows w*8 .. w*8+7 (mean) ----
        for (int j = 0; j < 8; ++j) {
            int r = warp * 8 + j;
            int row = block_row + r;
            float4 a0 = make_float4(0.f, 0.f, 0.f, 0.f);
            float4 a1 = a0, a2 = a0, a3 = a0;
            if (row < M) {
                int beg = g_off[row];
                int dg = g_degi[row];
                int i = 0;
                for (; i + 4 <= dg; i += 4) {
                    int s0 = g_ssrc[beg + i];
                    int s1 = g_ssrc[beg + i + 1];
                    int s2 = g_ssrc[beg + i + 2];
                    int s3 = g_ssrc[beg + i + 3];
                    float4 v0 = __ldg(reinterpret_cast<const float4*>(H + (size_t)s0 * D) + lane);
                    float4 v1 = __ldg(reinterpret_cast<const float4*>(H + (size_t)s1 * D) + lane);
                    float4 v2 = __ldg(reinterpret_cast<const float4*>(H + (size_t)s2 * D) + lane);
                    float4 v3 = __ldg(reinterpret_cast<const float4*>(H + (size_t)s3 * D) + lane);
                    a0.x += v0.x; a0.y += v0.y; a0.z += v0.z; a0.w += v0.w;
                    a1.x += v1.x; a1.y += v1.y; a1.z += v1.z; a1.w += v1.w;
                    a2.x += v2.x; a2.y += v2.y; a2.z += v2.z; a2.w += v2.w;
                    a3.x += v3.x; a3.y += v3.y; a3.z += v3.z; a3.w += v3.w;
                }
                for (; i < dg; ++i) {
                    int s = g_ssrc[beg + i];
                    float4 v = __ldg(reinterpret_cast<const float4*>(H + (size_t)s * D) + lane);
                    a0.x += v.x; a0.y += v.y; a0.z += v.z; a0.w += v.w;
                }
                float inv = (dg > 0) ? 1.0f / (float)dg : 0.0f;
                a0.x = (a0.x + a1.x + a2.x + a3.x) * inv;
                a0.y = (a0.y + a1.y + a2.y + a3.y) * inv;
                a0.z = (a0.z + a1.z + a2.z + a3.z) * inv;
                a0.w = (a0.w + a1.w + a2.w + a3.w) * inv;
            }
            u32 h0, l0, h1, l1;
            split2(a0.x, a0.y, h0, l0);
            split2(a0.z, a0.w, h1, l1);
            int o = r * AFS + lane * 2;
            As_hi[o] = h0; As_hi[o + 1] = h1;
            As_lo[o] = l0; As_lo[o + 1] = l1;
        }

        float acc[2][4][4];
#pragma unroll
        for (int i = 0; i < 2; ++i)
#pragma unroll
            for (int j = 0; j < 4; ++j)
#pragma unroll
                for (int r = 0; r < 4; ++r) acc[i][j][r] = 0.0f;

#pragma unroll 1
        for (int phase = 0; phase < 2; ++phase) {
            if (phase == 1) {
                __syncthreads();   // phase-0 A-frag reads done before overwrite
                for (int j = 0; j < 8; ++j) {
                    int r = warp * 8 + j;
                    int row = block_row + r;
                    float4 v = make_float4(0.f, 0.f, 0.f, 0.f);
                    if (row < M)
                        v = __ldg(reinterpret_cast<const float4*>(H + (size_t)row * D) + lane);
                    u32 h0, l0, h1, l1;
                    split2(v.x, v.y, h0, l0);
                    split2(v.z, v.w, h1, l1);
                    int o = r * AFS + lane * 2;
                    As_hi[o] = h0; As_hi[o + 1] = h1;
                    As_lo[o] = l0; As_lo[o + 1] = l1;
                }
            }
            const int kpbase = phase * 64;

#pragma unroll 1
            for (int k0 = 0; k0 < D; k0 += 32) {
                const int kc = k0 >> 1;   // packed-word base (0,16,32,48)
                const u32* bsh = Bhi + (size_t)(kpbase + kc + bkp) * 128 + bcn;
                const u32* bsl = Blo + (size_t)(kpbase + kc + bkp) * 128 + bcn;
                uint4 bh0 = __ldg(reinterpret_cast<const uint4*>(bsh));
                uint4 bh1 = __ldg(reinterpret_cast<const uint4*>(bsh + 4));
                uint4 bl0 = __ldg(reinterpret_cast<const uint4*>(bsl));
                uint4 bl1 = __ldg(reinterpret_cast<const uint4*>(bsl + 4));

                __syncthreads();   // prev chunk's Bs reads done; A stores visible
                {
                    u32 o = bkp * BS_STRIDE + bcn;
                    *reinterpret_cast<uint4*>(&Bs_hi[o]) = bh0;
                    *reinterpret_cast<uint4*>(&Bs_hi[o + 4]) = bh1;
                    *reinterpret_cast<uint4*>(&Bs_lo[o]) = bl0;
                    *reinterpret_cast<uint4*>(&Bs_lo[o + 4]) = bl1;
                }
                __syncthreads();

#pragma unroll
                for (int ks2 = 0; ks2 < 16; ks2 += 8) {
                    u32 bh[4][2], bl[4][2];
#pragma unroll
                    for (int nt = 0; nt < 4; ++nt) {
                        int nc = wn + nt * 8 + gid;
                        bh[nt][0] = Bs_hi[(ks2 + tig) * BS_STRIDE + nc];
                        bh[nt][1] = Bs_hi[(ks2 + tig + 4) * BS_STRIDE + nc];
                        bl[nt][0] = Bs_lo[(ks2 + tig) * BS_STRIDE + nc];
                        bl[nt][1] = Bs_lo[(ks2 + tig + 4) * BS_STRIDE + nc];
                    }
#pragma unroll
                    for (int mt = 0; mt < 2; ++mt) {
                        int rr0 = (wm + mt * 16 + gid) * AFS + kc;
                        int rr8 = rr0 + 8 * AFS;
                        u32 ah[4], al[4];
                        ah[0] = As_hi[rr0 + ks2 + tig];
                        ah[1] = As_hi[rr8 + ks2 + tig];
                        ah[2] = As_hi[rr0 + ks2 + tig + 4];
                        ah[3] = As_hi[rr8 + ks2 + tig + 4];
                        al[0] = As_lo[rr0 + ks2 + tig];
                        al[1] = As_lo[rr8 + ks2 + tig];
                        al[2] = As_lo[rr0 + ks2 + tig + 4];
                        al[3] = As_lo[rr8 + ks2 + tig + 4];
#pragma unroll
                        for (int nt = 0; nt < 4; ++nt) {
                            MMA_BF16(acc[mt][nt], ah, bh[nt]);
                            MMA_BF16(acc[mt][nt], ah, bl[nt]);
                            MMA_BF16(acc[mt][nt], al, bh[nt]);
                        }
                    }
                }
            }
        }

        // Epilogue: + mask(deg>0)*bias, optional ReLU, float2 stores.
#pragma unroll
        for (int mt = 0; mt < 2; ++mt) {
#pragma unroll
            for (int nt = 0; nt < 4; ++nt) {
                int row0 = block_row + wm + mt * 16 + gid;
                int row1 = row0 + 8;
                int col = wn + nt * 8 + tig * 2;
                float b0v = bias[col];
                float b1v = bias[col + 1];
                if (row0 < M) {
                    float m0 = (g_degi[row0] > 0) ? 1.0f : 0.0f;
                    float x0 = acc[mt][nt][0] + m0 * b0v;
                    float x1 = acc[mt][nt][1] + m0 * b1v;
                    if (RELU) { x0 = fmaxf(x0, 0.0f); x1 = fmaxf(x1, 0.0f); }
                    *reinterpret_cast<float2*>(out + (size_t)row0 * D + col) = make_float2(x0, x1);
                }
                if (row1 < M) {
                    float m1 = (g_degi[row1] > 0) ? 1.0f : 0.0f;
                    float x2 = acc[mt][nt][2] + m1 * b0v;
                    float x3 = acc[mt][nt][3] + m1 * b1v;
                    if (RELU) { x2 = fmaxf(x2, 0.0f); x3 = fmaxf(x3, 0.0f); }
                    *reinterpret_cast<float2*>(out + (size_t)row1 * D + col) = make_float2(x2, x3);
                }
            }
        }
    }
}

// ---------------------------------------------------------------------------
// Launch sequence (graph-capturable; all on default stream). 7 launches.
// ---------------------------------------------------------------------------
extern "C" void kernel_launch(void* const* d_in, const int* in_sizes, int n_in,
                              void* d_out, int out_size) {
    const float* x   = (const float*)d_in[0];
    const int*   ei  = (const int*)d_in[1];
    const float* W0l = (const float*)d_in[2];
    const float* b0l = (const float*)d_in[3];
    const float* W0r = (const float*)d_in[4];
    const float* W1l = (const float*)d_in[5];
    const float* b1l = (const float*)d_in[6];
    const float* W1r = (const float*)d_in[7];
    float* out = (float*)d_out;

    const int E = in_sizes[1] / 2;
    const int M = in_sizes[0] / D;
    const int* src = ei;
    const int* dst = ei + E;

    float* h_ptr = nullptr;
    u32* bp_ptr = nullptr;
    cudaGetSymbolAddress((void**)&h_ptr, g_h);
    cudaGetSymbolAddress((void**)&bp_ptr, g_Bp);

    cudaFuncSetAttribute(sage_fused_kernel<true>,
                         cudaFuncAttributeMaxDynamicSharedMemorySize, SMEM_BYTES);
    cudaFuncSetAttribute(sage_fused_kernel<false>,
                         cudaFuncAttributeMaxDynamicSharedMemorySize, SMEM_BYTES);

    const int eb4 = (E / 4 + 255) / 256 + 1;
    const int scanb = (M + SCAN_BLK - 1) / SCAN_BLK;
    const int ntiles = (M + 63) / 64;
    const int workers = 444 < ntiles ? 444 : ntiles;   // 3 CTAs/SM x 148 SMs
    const size_t plane = (size_t)128 * 128;

    // Setup: weights (+zero deg/counters) -> count -> scan -> fill
    convert_w_zero_kernel<<<256, 128>>>(W0l, W0r, W1l, W1r, M);
    count_deg_kernel<<<eb4, 256>>>(dst, E);
    scan_part_kernel<<<scanb, SCAN_BLK>>>(M);
    scan_write_kernel<<<scanb, SCAN_BLK>>>(M);
    fill_csr_kernel<<<eb4, 256>>>(src, dst, E);

    // Layer 0: fused gather + GEMM (+ReLU), persistent work-stealing
    sage_fused_kernel<true><<<workers, 256, SMEM_BYTES>>>(
        x, bp_ptr, bp_ptr + plane, b0l, h_ptr, M, ntiles, 0);

    // Layer 1: fused gather + GEMM
    sage_fused_kernel<false><<<workers, 256, SMEM_BYTES>>>(
        h_ptr, bp_ptr + 2 * plane, bp_ptr + 3 * plane, b1l, out, M, ntiles, 1);
}

// round 12
// speedup vs baseline: 1.0325x; 1.0325x over previous
#include <cuda_runtime.h>
#include <cuda_bf16.h>
#include <cstddef>
#include <cstdint>

#define D 128
#define MAX_NODES 50000
#define MAX_EDGES 800000

typedef unsigned int u32;

// Static device scratch (no allocations allowed).
__device__ float g_h[(size_t)MAX_NODES * D];     // layer-0 output
__device__ int   g_degi[MAX_NODES];
__device__ int   g_off[MAX_NODES];
__device__ int   g_cur[MAX_NODES];
__device__ int   g_ssrc[MAX_EDGES];
__device__ int   g_part[64];
// Pre-split packed weights: [layer][plane hi/lo][kp][n], u32 = bf16x2(k=2kp,k=2kp+1).
__device__ u32 g_Bp[2][2][128][128];

// ---------------------------------------------------------------------------
// Weight conversion + zero g_degi (runs before count_deg; saves one launch).
// grid = 256 (layer*128 + kp), block = 128 (n).
// ---------------------------------------------------------------------------
__global__ void convert_w_zero_kernel(const float* __restrict__ W0l,
                                      const float* __restrict__ W0r,
                                      const float* __restrict__ W1l,
                                      const float* __restrict__ W1r,
                                      int M) {
    int kp = blockIdx.x & 127;
    int layer = blockIdx.x >> 7;
    int n = threadIdx.x;
    int k0 = 2 * kp;
    const float* W = layer ? (k0 < D ? W1l : W1r) : (k0 < D ? W0l : W0r);
    float v0 = W[(size_t)(k0 & (D - 1)) * D + n];
    float v1 = W[(size_t)((k0 + 1) & (D - 1)) * D + n];
    __nv_bfloat162 h2 = __floats2bfloat162_rn(v0, v1);
    float hx = __bfloat162float(__low2bfloat16(h2));
    float hy = __bfloat162float(__high2bfloat16(h2));
    __nv_bfloat162 l2 = __floats2bfloat162_rn(v0 - hx, v1 - hy);
    g_Bp[layer][0][kp][n] = *reinterpret_cast<u32*>(&h2);
    g_Bp[layer][1][kp][n] = *reinterpret_cast<u32*>(&l2);

    int idx = blockIdx.x * 128 + n;          // 32768 threads, 2 strides cover 50k
    if (idx < M) g_degi[idx] = 0;
    idx += 32768;
    if (idx < M) g_degi[idx] = 0;
}

__global__ void count_deg_kernel(const int* __restrict__ dst, int E) {
    int i = (blockIdx.x * blockDim.x + threadIdx.x) * 4;
    if (i + 4 <= E) {
        int4 d = *reinterpret_cast<const int4*>(dst + i);
        atomicAdd(&g_degi[d.x], 1);
        atomicAdd(&g_degi[d.y], 1);
        atomicAdd(&g_degi[d.z], 1);
        atomicAdd(&g_degi[d.w], 1);
    } else {
        for (; i < E; ++i) atomicAdd(&g_degi[dst[i]], 1);
    }
}

#define SCAN_BLK 1024
__global__ void scan_part_kernel(int n) {
    __shared__ int red[SCAN_BLK];
    int tid = threadIdx.x;
    int i = blockIdx.x * SCAN_BLK + tid;
    red[tid] = (i < n) ? g_degi[i] : 0;
    __syncthreads();
#pragma unroll
    for (int ofs = SCAN_BLK / 2; ofs > 0; ofs >>= 1) {
        if (tid < ofs) red[tid] += red[tid + ofs];
        __syncthreads();
    }
    if (tid == 0) g_part[blockIdx.x] = red[0];
}

// Block scan + serial base accumulation (<=48 adds per block << launch latency).
__global__ void scan_write_kernel(int n) {
    __shared__ int s[SCAN_BLK];
    __shared__ int sbase;
    int tid = threadIdx.x;
    int i = blockIdx.x * SCAN_BLK + tid;
    int v = (i < n) ? g_degi[i] : 0;
    s[tid] = v;
    if (tid == 0) {
        int run = 0;
        for (int b = 0; b < blockIdx.x; ++b) run += g_part[b];
        sbase = run;
    }
    __syncthreads();
    for (int ofs = 1; ofs < SCAN_BLK; ofs <<= 1) {
        int t = (tid >= ofs) ? s[tid - ofs] : 0;
        __syncthreads();
        s[tid] += t;
        __syncthreads();
    }
    int excl = s[tid] - v + sbase;
    if (i < n) { g_off[i] = excl; g_cur[i] = excl; }
}

__global__ void fill_csr_kernel(const int* __restrict__ src,
                                const int* __restrict__ dst, int E) {
    int i = (blockIdx.x * blockDim.x + threadIdx.x) * 4;
    if (i + 4 <= E) {
        int4 d = *reinterpret_cast<const int4*>(dst + i);
        int4 s = *reinterpret_cast<const int4*>(src + i);
        // 4 independent atomic->store chains (latency-bound kernel; MLP=4)
        int p0 = atomicAdd(&g_cur[d.x], 1);
        int p1 = atomicAdd(&g_cur[d.y], 1);
        int p2 = atomicAdd(&g_cur[d.z], 1);
        int p3 = atomicAdd(&g_cur[d.w], 1);
        g_ssrc[p0] = s.x;
        g_ssrc[p1] = s.y;
        g_ssrc[p2] = s.z;
        g_ssrc[p3] = s.w;
    } else {
        for (; i < E; ++i) g_ssrc[atomicAdd(&g_cur[dst[i]], 1)] = src[i];
    }
}

// ---------------------------------------------------------------------------
// Fused gather + SAGE GEMM (3xBF16 mma.sync.m16n8k16), BM=64 x BN=128 tiles.
// Static grid (R10 champion): one CTA per tile; CLC scheduler balances.
//   Phase 0: A = mean-gather of H over CSR neighbors (all warps gather —
//            full-SM participation required to saturate L2 BW).
//   Phase 1: A = H rows (skip path).
//   out = A0@Wl + A1@Wr + mask(deg>0).*bias (+ReLU).
// ---------------------------------------------------------------------------
#define MMA_BF16(c, a, b)                                                      \
    asm volatile(                                                              \
        "mma.sync.aligned.m16n8k16.row.col.f32.bf16.bf16.f32 "                 \
        "{%0,%1,%2,%3},{%4,%5,%6,%7},{%8,%9},{%0,%1,%2,%3};"                   \
        : "+f"((c)[0]), "+f"((c)[1]), "+f"((c)[2]), "+f"((c)[3])               \
        : "r"((a)[0]), "r"((a)[1]), "r"((a)[2]), "r"((a)[3]),                  \
          "r"((b)[0]), "r"((b)[1]))

#define AFS 68          // full-K A stride: 64 packed words + 4 pad
#define BS_STRIDE 136   // B chunk stride: 128 packed cols + 8 pad
#define SMEM_WORDS (2 * 64 * AFS + 2 * 16 * BS_STRIDE)
#define SMEM_BYTES (SMEM_WORDS * 4)

__device__ __forceinline__ void split2(float x, float y, u32& hi, u32& lo) {
    __nv_bfloat162 h2 = __floats2bfloat162_rn(x, y);
    float hx = __bfloat162float(__low2bfloat16(h2));
    float hy = __bfloat162float(__high2bfloat16(h2));
    __nv_bfloat162 l2 = __floats2bfloat162_rn(x - hx, y - hy);
    hi = *reinterpret_cast<u32*>(&h2);
    lo = *reinterpret_cast<u32*>(&l2);
}

template <bool RELU>
__global__ void __launch_bounds__(256, 3)
sage_fused_kernel(const float* __restrict__ H,
                  const u32* __restrict__ Bhi, const u32* __restrict__ Blo,
                  const float* __restrict__ bias, float* __restrict__ out,
                  int M) {
    extern __shared__ u32 sm[];
    u32* As_hi = sm;                             // 64 * AFS
    u32* As_lo = sm + 64 * AFS;
    u32* Bs_hi = sm + 2 * 64 * AFS;              // 16 * BS_STRIDE
    u32* Bs_lo = sm + 2 * 64 * AFS + 16 * BS_STRIDE;

    const int tid = threadIdx.x;
    const int warp = tid >> 5;
    const int lane = tid & 31;
    const int gid = lane >> 2;
    const int tig = lane & 3;
    const int wm = (warp >> 2) * 32;
    const int wn = (warp & 3) * 32;
    const int block_row = blockIdx.x * 64;

    const int bkp = tid >> 4;            // B staging: packed-k row 0..15
    const int bcn = (tid & 15) * 8;      //           8 cols per thread

    // ---- gather phase: warp w produces A rows w*8 .. w*8+7 (mean of nbrs) ----
    for (int j = 0; j < 8; ++j) {
        int r = warp * 8 + j;
        int row = block_row + r;
        float4 a0 = make_float4(0.f, 0.f, 0.f, 0.f);
        float4 a1 = a0, a2 = a0, a3 = a0;
        if (row < M) {
            int beg = g_off[row];
            int dg = g_degi[row];
            int i = 0;
            for (; i + 4 <= dg; i += 4) {
                int s0 = g_ssrc[beg + i];
                int s1 = g_ssrc[beg + i + 1];
                int s2 = g_ssrc[beg + i + 2];
                int s3 = g_ssrc[beg + i + 3];
                float4 v0 = __ldg(reinterpret_cast<const float4*>(H + (size_t)s0 * D) + lane);
                float4 v1 = __ldg(reinterpret_cast<const float4*>(H + (size_t)s1 * D) + lane);
                float4 v2 = __ldg(reinterpret_cast<const float4*>(H + (size_t)s2 * D) + lane);
                float4 v3 = __ldg(reinterpret_cast<const float4*>(H + (size_t)s3 * D) + lane);
                a0.x += v0.x; a0.y += v0.y; a0.z += v0.z; a0.w += v0.w;
                a1.x += v1.x; a1.y += v1.y; a1.z += v1.z; a1.w += v1.w;
                a2.x += v2.x; a2.y += v2.y; a2.z += v2.z; a2.w += v2.w;
                a3.x += v3.x; a3.y += v3.y; a3.z += v3.z; a3.w += v3.w;
            }
            for (; i < dg; ++i) {
                int s = g_ssrc[beg + i];
                float4 v = __ldg(reinterpret_cast<const float4*>(H + (size_t)s * D) + lane);
                a0.x += v.x; a0.y += v.y; a0.z += v.z; a0.w += v.w;
            }
            float inv = (dg > 0) ? 1.0f / (float)dg : 0.0f;
            a0.x = (a0.x + a1.x + a2.x + a3.x) * inv;
            a0.y = (a0.y + a1.y + a2.y + a3.y) * inv;
            a0.z = (a0.z + a1.z + a2.z + a3.z) * inv;
            a0.w = (a0.w + a1.w + a2.w + a3.w) * inv;
        }
        u32 h0, l0, h1, l1;
        split2(a0.x, a0.y, h0, l0);
        split2(a0.z, a0.w, h1, l1);
        int o = r * AFS + lane * 2;
        As_hi[o] = h0; As_hi[o + 1] = h1;
        As_lo[o] = l0; As_lo[o + 1] = l1;
    }

    float acc[2][4][4];
#pragma unroll
    for (int i = 0; i < 2; ++i)
#pragma unroll
        for (int j = 0; j < 4; ++j)
#pragma unroll
            for (int r = 0; r < 4; ++r) acc[i][j][r] = 0.0f;

#pragma unroll 1
    for (int phase = 0; phase < 2; ++phase) {
        if (phase == 1) {
            __syncthreads();   // all phase-0 A-frag reads done before overwrite
            // restage A = H rows (skip path)
            for (int j = 0; j < 8; ++j) {
                int r = warp * 8 + j;
                int row = block_row + r;
                float4 v = make_float4(0.f, 0.f, 0.f, 0.f);
                if (row < M)
                    v = __ldg(reinterpret_cast<const float4*>(H + (size_t)row * D) + lane);
                u32 h0, l0, h1, l1;
                split2(v.x, v.y, h0, l0);
                split2(v.z, v.w, h1, l1);
                int o = r * AFS + lane * 2;
                As_hi[o] = h0; As_hi[o + 1] = h1;
                As_lo[o] = l0; As_lo[o + 1] = l1;
            }
        }
        const int kpbase = phase * 64;

#pragma unroll 1
        for (int k0 = 0; k0 < D; k0 += 32) {
            const int kc = k0 >> 1;   // packed-word base of this chunk (0,16,32,48)
            const u32* bsh = Bhi + (size_t)(kpbase + kc + bkp) * 128 + bcn;
            const u32* bsl = Blo + (size_t)(kpbase + kc + bkp) * 128 + bcn;
            uint4 bh0 = __ldg(reinterpret_cast<const uint4*>(bsh));
            uint4 bh1 = __ldg(reinterpret_cast<const uint4*>(bsh + 4));
            uint4 bl0 = __ldg(reinterpret_cast<const uint4*>(bsl));
            uint4 bl1 = __ldg(reinterpret_cast<const uint4*>(bsl + 4));

            __syncthreads();   // previous chunk's Bs reads done; A stores visible
            {
                u32 o = bkp * BS_STRIDE + bcn;
                *reinterpret_cast<uint4*>(&Bs_hi[o]) = bh0;
                *reinterpret_cast<uint4*>(&Bs_hi[o + 4]) = bh1;
                *reinterpret_cast<uint4*>(&Bs_lo[o]) = bl0;
                *reinterpret_cast<uint4*>(&Bs_lo[o + 4]) = bl1;
            }
            __syncthreads();

#pragma unroll
            for (int ks2 = 0; ks2 < 16; ks2 += 8) {
                u32 bh[4][2], bl[4][2];
#pragma unroll
                for (int nt = 0; nt < 4; ++nt) {
                    int nc = wn + nt * 8 + gid;
                    bh[nt][0] = Bs_hi[(ks2 + tig) * BS_STRIDE + nc];
                    bh[nt][1] = Bs_hi[(ks2 + tig + 4) * BS_STRIDE + nc];
                    bl[nt][0] = Bs_lo[(ks2 + tig) * BS_STRIDE + nc];
                    bl[nt][1] = Bs_lo[(ks2 + tig + 4) * BS_STRIDE + nc];
                }
#pragma unroll
                for (int mt = 0; mt < 2; ++mt) {
                    int rr0 = (wm + mt * 16 + gid) * AFS + kc;
                    int rr8 = rr0 + 8 * AFS;
                    u32 ah[4], al[4];
                    ah[0] = As_hi[rr0 + ks2 + tig];
                    ah[1] = As_hi[rr8 + ks2 + tig];
                    ah[2] = As_hi[rr0 + ks2 + tig + 4];
                    ah[3] = As_hi[rr8 + ks2 + tig + 4];
                    al[0] = As_lo[rr0 + ks2 + tig];
                    al[1] = As_lo[rr8 + ks2 + tig];
                    al[2] = As_lo[rr0 + ks2 + tig + 4];
                    al[3] = As_lo[rr8 + ks2 + tig + 4];
#pragma unroll
                    for (int nt = 0; nt < 4; ++nt) {
                        MMA_BF16(acc[mt][nt], ah, bh[nt]);
                        MMA_BF16(acc[mt][nt], ah, bl[nt]);
                        MMA_BF16(acc[mt][nt], al, bh[nt]);
                    }
                }
            }
        }
    }

    // Epilogue: + mask(deg>0)*bias, optional ReLU, float2 stores.
#pragma unroll
    for (int mt = 0; mt < 2; ++mt) {
#pragma unroll
        for (int nt = 0; nt < 4; ++nt) {
            int row0 = block_row + wm + mt * 16 + gid;
            int row1 = row0 + 8;
            int col = wn + nt * 8 + tig * 2;
            float b0v = bias[col];
            float b1v = bias[col + 1];
            if (row0 < M) {
                float m0 = (g_degi[row0] > 0) ? 1.0f : 0.0f;
                float x0 = acc[mt][nt][0] + m0 * b0v;
                float x1 = acc[mt][nt][1] + m0 * b1v;
                if (RELU) { x0 = fmaxf(x0, 0.0f); x1 = fmaxf(x1, 0.0f); }
                *reinterpret_cast<float2*>(out + (size_t)row0 * D + col) = make_float2(x0, x1);
            }
            if (row1 < M) {
                float m1 = (g_degi[row1] > 0) ? 1.0f : 0.0f;
                float x2 = acc[mt][nt][2] + m1 * b0v;
                float x3 = acc[mt][nt][3] + m1 * b1v;
                if (RELU) { x2 = fmaxf(x2, 0.0f); x3 = fmaxf(x3, 0.0f); }
                *reinterpret_cast<float2*>(out + (size_t)row1 * D + col) = make_float2(x2, x3);
            }
        }
    }
}

// ---------------------------------------------------------------------------
// Launch sequence (graph-capturable; all on default stream). 7 launches.
// ---------------------------------------------------------------------------
extern "C" void kernel_launch(void* const* d_in, const int* in_sizes, int n_in,
                              void* d_out, int out_size) {
    const float* x   = (const float*)d_in[0];
    const int*   ei  = (const int*)d_in[1];
    const float* W0l = (const float*)d_in[2];
    const float* b0l = (const float*)d_in[3];
    const float* W0r = (const float*)d_in[4];
    const float* W1l = (const float*)d_in[5];
    const float* b1l = (const float*)d_in[6];
    const float* W1r = (const float*)d_in[7];
    float* out = (float*)d_out;

    const int E = in_sizes[1] / 2;
    const int M = in_sizes[0] / D;
    const int* src = ei;
    const int* dst = ei + E;

    float* h_ptr = nullptr;
    u32* bp_ptr = nullptr;
    cudaGetSymbolAddress((void**)&h_ptr, g_h);
    cudaGetSymbolAddress((void**)&bp_ptr, g_Bp);

    cudaFuncSetAttribute(sage_fused_kernel<true>,
                         cudaFuncAttributeMaxDynamicSharedMemorySize, SMEM_BYTES);
    cudaFuncSetAttribute(sage_fused_kernel<false>,
                         cudaFuncAttributeMaxDynamicSharedMemorySize, SMEM_BYTES);

    const int eb4 = (E / 4 + 255) / 256 + 1;
    const int scanb = (M + SCAN_BLK - 1) / SCAN_BLK;
    const int gemmb = (M + 63) / 64;
    const size_t plane = (size_t)128 * 128;

    // Setup: weights (+zero deg) -> count -> scan(2) -> fill
    convert_w_zero_kernel<<<256, 128>>>(W0l, W0r, W1l, W1r, M);
    count_deg_kernel<<<eb4, 256>>>(dst, E);
    scan_part_kernel<<<scanb, SCAN_BLK>>>(M);
    scan_write_kernel<<<scanb, SCAN_BLK>>>(M);
    fill_csr_kernel<<<eb4, 256>>>(src, dst, E);

    // Layer 0: fused gather + GEMM (+ReLU)
    sage_fused_kernel<true><<<gemmb, 256, SMEM_BYTES>>>(
        x, bp_ptr, bp_ptr + plane, b0l, h_ptr, M);

    // Layer 1: fused gather + GEMM
    sage_fused_kernel<false><<<gemmb, 256, SMEM_BYTES>>>(
        h_ptr, bp_ptr + 2 * plane, bp_ptr + 3 * plane, b1l, out, M);
}

// round 13
// speedup vs baseline: 1.1198x; 1.0845x over previous
#include <cuda_runtime.h>
#include <cuda_fp16.h>
#include <cstddef>
#include <cstdint>

#define D 128
#define MAX_NODES 50000
#define MAX_EDGES 800000

typedef unsigned int u32;

// Static device scratch (no allocations allowed).
__device__ float g_h[(size_t)MAX_NODES * D];     // layer-0 output
__device__ int   g_degi[MAX_NODES];
__device__ int   g_off[MAX_NODES];
__device__ int   g_cur[MAX_NODES];
__device__ int   g_ssrc[MAX_EDGES];
__device__ int   g_part[64];
// Pre-split packed weights: [layer][plane hi/lo][kp][n], u32 = half2(k=2kp,k=2kp+1).
__device__ u32 g_Bp[2][2][128][128];

// ---------------------------------------------------------------------------
// Weight conversion (fp16 hi + lo residual) + zero g_degi.
// grid = 256 (layer*128 + kp), block = 128 (n).
// ---------------------------------------------------------------------------
__global__ void convert_w_zero_kernel(const float* __restrict__ W0l,
                                      const float* __restrict__ W0r,
                                      const float* __restrict__ W1l,
                                      const float* __restrict__ W1r,
                                      int M) {
    int kp = blockIdx.x & 127;
    int layer = blockIdx.x >> 7;
    int n = threadIdx.x;
    int k0 = 2 * kp;
    const float* W = layer ? (k0 < D ? W1l : W1r) : (k0 < D ? W0l : W0r);
    float v0 = W[(size_t)(k0 & (D - 1)) * D + n];
    float v1 = W[(size_t)((k0 + 1) & (D - 1)) * D + n];
    __half2 h2 = __floats2half2_rn(v0, v1);
    float hx = __low2float(h2);
    float hy = __high2float(h2);
    __half2 l2 = __floats2half2_rn(v0 - hx, v1 - hy);
    g_Bp[layer][0][kp][n] = *reinterpret_cast<u32*>(&h2);
    g_Bp[layer][1][kp][n] = *reinterpret_cast<u32*>(&l2);

    int idx = blockIdx.x * 128 + n;          // 32768 threads, 2 strides cover 50k
    if (idx < M) g_degi[idx] = 0;
    idx += 32768;
    if (idx < M) g_degi[idx] = 0;
}

__global__ void count_deg_kernel(const int* __restrict__ dst, int E) {
    int i = (blockIdx.x * blockDim.x + threadIdx.x) * 4;
    if (i + 4 <= E) {
        int4 d = *reinterpret_cast<const int4*>(dst + i);
        atomicAdd(&g_degi[d.x], 1);
        atomicAdd(&g_degi[d.y], 1);
        atomicAdd(&g_degi[d.z], 1);
        atomicAdd(&g_degi[d.w], 1);
    } else {
        for (; i < E; ++i) atomicAdd(&g_degi[dst[i]], 1);
    }
}

#define SCAN_BLK 1024
__global__ void scan_part_kernel(int n) {
    __shared__ int red[SCAN_BLK];
    int tid = threadIdx.x;
    int i = blockIdx.x * SCAN_BLK + tid;
    red[tid] = (i < n) ? g_degi[i] : 0;
    __syncthreads();
#pragma unroll
    for (int ofs = SCAN_BLK / 2; ofs > 0; ofs >>= 1) {
        if (tid < ofs) red[tid] += red[tid + ofs];
        __syncthreads();
    }
    if (tid == 0) g_part[blockIdx.x] = red[0];
}

// Block scan + serial base accumulation (<=48 adds per block << launch latency).
__global__ void scan_write_kernel(int n) {
    __shared__ int s[SCAN_BLK];
    __shared__ int sbase;
    int tid = threadIdx.x;
    int i = blockIdx.x * SCAN_BLK + tid;
    int v = (i < n) ? g_degi[i] : 0;
    s[tid] = v;
    if (tid == 0) {
        int run = 0;
        for (int b = 0; b < blockIdx.x; ++b) run += g_part[b];
        sbase = run;
    }
    __syncthreads();
    for (int ofs = 1; ofs < SCAN_BLK; ofs <<= 1) {
        int t = (tid >= ofs) ? s[tid - ofs] : 0;
        __syncthreads();
        s[tid] += t;
        __syncthreads();
    }
    int excl = s[tid] - v + sbase;
    if (i < n) { g_off[i] = excl; g_cur[i] = excl; }
}

__global__ void fill_csr_kernel(const int* __restrict__ src,
                                const int* __restrict__ dst, int E) {
    int i = (blockIdx.x * blockDim.x + threadIdx.x) * 4;
    if (i + 4 <= E) {
        int4 d = *reinterpret_cast<const int4*>(dst + i);
        int4 s = *reinterpret_cast<const int4*>(src + i);
        int p0 = atomicAdd(&g_cur[d.x], 1);
        int p1 = atomicAdd(&g_cur[d.y], 1);
        int p2 = atomicAdd(&g_cur[d.z], 1);
        int p3 = atomicAdd(&g_cur[d.w], 1);
        g_ssrc[p0] = s.x;
        g_ssrc[p1] = s.y;
        g_ssrc[p2] = s.z;
        g_ssrc[p3] = s.w;
    } else {
        for (; i < E; ++i) g_ssrc[atomicAdd(&g_cur[dst[i]], 1)] = src[i];
    }
}

// ---------------------------------------------------------------------------
// Fused gather + SAGE GEMM (2x FP16 mma.sync.m16n8k16), BM=64 x BN=128 tiles.
//   A (agg / h rows) rounded to a single fp16 plane; B = fp16 hi + lo planes.
//   out ~= Ah@(Bh+Bl) per phase: 2 MMAs per k-step (was 3 with bf16 split).
//   Phase 0: A = mean-gather of H over CSR neighbors (all warps gather).
//   Phase 1: A = H rows (skip path).
//   out = A0@Wl + A1@Wr + mask(deg>0).*bias (+ReLU).
// Smem 34.8KB/CTA -> 4 CTAs/SM (32 warps: more gather MLP + phase overlap).
// ---------------------------------------------------------------------------
#define MMA_F16(c, a, b)                                                       \
    asm volatile(                                                              \
        "mma.sync.aligned.m16n8k16.row.col.f32.f16.f16.f32 "                   \
        "{%0,%1,%2,%3},{%4,%5,%6,%7},{%8,%9},{%0,%1,%2,%3};"                   \
        : "+f"((c)[0]), "+f"((c)[1]), "+f"((c)[2]), "+f"((c)[3])               \
        : "r"((a)[0]), "r"((a)[1]), "r"((a)[2]), "r"((a)[3]),                  \
          "r"((b)[0]), "r"((b)[1]))

#define AFS 68          // full-K A stride: 64 packed words + 4 pad
#define BS_STRIDE 136   // B chunk stride: 128 packed cols + 8 pad
#define SMEM_WORDS (64 * AFS + 2 * 16 * BS_STRIDE)
#define SMEM_BYTES (SMEM_WORDS * 4)

__device__ __forceinline__ u32 pack_h2(float x, float y) {
    __half2 h = __floats2half2_rn(x, y);
    return *reinterpret_cast<u32*>(&h);
}

template <bool RELU>
__global__ void __launch_bounds__(256, 4)
sage_fused_kernel(const float* __restrict__ H,
                  const u32* __restrict__ Bhi, const u32* __restrict__ Blo,
                  const float* __restrict__ bias, float* __restrict__ out,
                  int M) {
    extern __shared__ u32 sm[];
    u32* As = sm;                                // 64 * AFS (single fp16 plane)
    u32* Bs_hi = sm + 64 * AFS;                  // 16 * BS_STRIDE
    u32* Bs_lo = sm + 64 * AFS + 16 * BS_STRIDE;

    const int tid = threadIdx.x;
    const int warp = tid >> 5;
    const int lane = tid & 31;
    const int gid = lane >> 2;
    const int tig = lane & 3;
    const int wm = (warp >> 2) * 32;
    const int wn = (warp & 3) * 32;
    const int block_row = blockIdx.x * 64;

    const int bkp = tid >> 4;            // B staging: packed-k row 0..15
    const int bcn = (tid & 15) * 8;      //           8 cols per thread

    // ---- gather phase: warp w produces A rows w*8 .. w*8+7 (mean of nbrs) ----
    for (int j = 0; j < 8; ++j) {
        int r = warp * 8 + j;
        int row = block_row + r;
        float4 a0 = make_float4(0.f, 0.f, 0.f, 0.f);
        float4 a1 = a0, a2 = a0, a3 = a0;
        if (row < M) {
            int beg = g_off[row];
            int dg = g_degi[row];
            int i = 0;
            for (; i + 4 <= dg; i += 4) {
                int s0 = g_ssrc[beg + i];
                int s1 = g_ssrc[beg + i + 1];
                int s2 = g_ssrc[beg + i + 2];
                int s3 = g_ssrc[beg + i + 3];
                float4 v0 = __ldg(reinterpret_cast<const float4*>(H + (size_t)s0 * D) + lane);
                float4 v1 = __ldg(reinterpret_cast<const float4*>(H + (size_t)s1 * D) + lane);
                float4 v2 = __ldg(reinterpret_cast<const float4*>(H + (size_t)s2 * D) + lane);
                float4 v3 = __ldg(reinterpret_cast<const float4*>(H + (size_t)s3 * D) + lane);
                a0.x += v0.x; a0.y += v0.y; a0.z += v0.z; a0.w += v0.w;
                a1.x += v1.x; a1.y += v1.y; a1.z += v1.z; a1.w += v1.w;
                a2.x += v2.x; a2.y += v2.y; a2.z += v2.z; a2.w += v2.w;
                a3.x += v3.x; a3.y += v3.y; a3.z += v3.z; a3.w += v3.w;
            }
            for (; i < dg; ++i) {
                int s = g_ssrc[beg + i];
                float4 v = __ldg(reinterpret_cast<const float4*>(H + (size_t)s * D) + lane);
                a0.x += v.x; a0.y += v.y; a0.z += v.z; a0.w += v.w;
            }
            float inv = (dg > 0) ? 1.0f / (float)dg : 0.0f;
            a0.x = (a0.x + a1.x + a2.x + a3.x) * inv;
            a0.y = (a0.y + a1.y + a2.y + a3.y) * inv;
            a0.z = (a0.z + a1.z + a2.z + a3.z) * inv;
            a0.w = (a0.w + a1.w + a2.w + a3.w) * inv;
        }
        int o = r * AFS + lane * 2;
        As[o] = pack_h2(a0.x, a0.y);
        As[o + 1] = pack_h2(a0.z, a0.w);
    }

    float acc[2][4][4];
#pragma unroll
    for (int i = 0; i < 2; ++i)
#pragma unroll
        for (int j = 0; j < 4; ++j)
#pragma unroll
            for (int r = 0; r < 4; ++r) acc[i][j][r] = 0.0f;

#pragma unroll 1
    for (int phase = 0; phase < 2; ++phase) {
        if (phase == 1) {
            __syncthreads();   // all phase-0 A-frag reads done before overwrite
            // restage A = H rows (skip path)
            for (int j = 0; j < 8; ++j) {
                int r = warp * 8 + j;
                int row = block_row + r;
                float4 v = make_float4(0.f, 0.f, 0.f, 0.f);
                if (row < M)
                    v = __ldg(reinterpret_cast<const float4*>(H + (size_t)row * D) + lane);
                int o = r * AFS + lane * 2;
                As[o] = pack_h2(v.x, v.y);
                As[o + 1] = pack_h2(v.z, v.w);
            }
        }
        const int kpbase = phase * 64;

#pragma unroll 1
        for (int k0 = 0; k0 < D; k0 += 32) {
            const int kc = k0 >> 1;   // packed-word base of this chunk (0,16,32,48)
            const u32* bsh = Bhi + (size_t)(kpbase + kc + bkp) * 128 + bcn;
            const u32* bsl = Blo + (size_t)(kpbase + kc + bkp) * 128 + bcn;
            uint4 bh0 = __ldg(reinterpret_cast<const uint4*>(bsh));
            uint4 bh1 = __ldg(reinterpret_cast<const uint4*>(bsh + 4));
            uint4 bl0 = __ldg(reinterpret_cast<const uint4*>(bsl));
            uint4 bl1 = __ldg(reinterpret_cast<const uint4*>(bsl + 4));

            __syncthreads();   // previous chunk's Bs reads done; A stores visible
            {
                u32 o = bkp * BS_STRIDE + bcn;
                *reinterpret_cast<uint4*>(&Bs_hi[o]) = bh0;
                *reinterpret_cast<uint4*>(&Bs_hi[o + 4]) = bh1;
                *reinterpret_cast<uint4*>(&Bs_lo[o]) = bl0;
                *reinterpret_cast<uint4*>(&Bs_lo[o + 4]) = bl1;
            }
            __syncthreads();

#pragma unroll
            for (int ks2 = 0; ks2 < 16; ks2 += 8) {
                u32 bh[4][2], bl[4][2];
#pragma unroll
                for (int nt = 0; nt < 4; ++nt) {
                    int nc = wn + nt * 8 + gid;
                    bh[nt][0] = Bs_hi[(ks2 + tig) * BS_STRIDE + nc];
                    bh[nt][1] = Bs_hi[(ks2 + tig + 4) * BS_STRIDE + nc];
                    bl[nt][0] = Bs_lo[(ks2 + tig) * BS_STRIDE + nc];
                    bl[nt][1] = Bs_lo[(ks2 + tig + 4) * BS_STRIDE + nc];
                }
#pragma unroll
                for (int mt = 0; mt < 2; ++mt) {
                    int rr0 = (wm + mt * 16 + gid) * AFS + kc;
                    int rr8 = rr0 + 8 * AFS;
                    u32 ah[4];
                    ah[0] = As[rr0 + ks2 + tig];
                    ah[1] = As[rr8 + ks2 + tig];
                    ah[2] = As[rr0 + ks2 + tig + 4];
                    ah[3] = As[rr8 + ks2 + tig + 4];
#pragma unroll
                    for (int nt = 0; nt < 4; ++nt) {
                        MMA_F16(acc[mt][nt], ah, bh[nt]);
                        MMA_F16(acc[mt][nt], ah, bl[nt]);
                    }
                }
            }
        }
    }

    // Epilogue: + mask(deg>0)*bias, optional ReLU, float2 stores.
#pragma unroll
    for (int mt = 0; mt < 2; ++mt) {
#pragma unroll
        for (int nt = 0; nt < 4; ++nt) {
            int row0 = block_row + wm + mt * 16 + gid;
            int row1 = row0 + 8;
            int col = wn + nt * 8 + tig * 2;
            float b0v = bias[col];
            float b1v = bias[col + 1];
            if (row0 < M) {
                float m0 = (g_degi[row0] > 0) ? 1.0f : 0.0f;
                float x0 = acc[mt][nt][0] + m0 * b0v;
                float x1 = acc[mt][nt][1] + m0 * b1v;
                if (RELU) { x0 = fmaxf(x0, 0.0f); x1 = fmaxf(x1, 0.0f); }
                *reinterpret_cast<float2*>(out + (size_t)row0 * D + col) = make_float2(x0, x1);
            }
            if (row1 < M) {
                float m1 = (g_degi[row1] > 0) ? 1.0f : 0.0f;
                float x2 = acc[mt][nt][2] + m1 * b0v;
                float x3 = acc[mt][nt][3] + m1 * b1v;
                if (RELU) { x2 = fmaxf(x2, 0.0f); x3 = fmaxf(x3, 0.0f); }
                *reinterpret_cast<float2*>(out + (size_t)row1 * D + col) = make_float2(x2, x3);
            }
        }
    }
}

// ---------------------------------------------------------------------------
// Launch sequence (graph-capturable; all on default stream). 7 launches.
// ---------------------------------------------------------------------------
extern "C" void kernel_launch(void* const* d_in, const int* in_sizes, int n_in,
                              void* d_out, int out_size) {
    const float* x   = (const float*)d_in[0];
    const int*   ei  = (const int*)d_in[1];
    const float* W0l = (const float*)d_in[2];
    const float* b0l = (const float*)d_in[3];
    const float* W0r = (const float*)d_in[4];
    const float* W1l = (const float*)d_in[5];
    const float* b1l = (const float*)d_in[6];
    const float* W1r = (const float*)d_in[7];
    float* out = (float*)d_out;

    const int E = in_sizes[1] / 2;
    const int M = in_sizes[0] / D;
    const int* src = ei;
    const int* dst = ei + E;

    float* h_ptr = nullptr;
    u32* bp_ptr = nullptr;
    cudaGetSymbolAddress((void**)&h_ptr, g_h);
    cudaGetSymbolAddress((void**)&bp_ptr, g_Bp);

    cudaFuncSetAttribute(sage_fused_kernel<true>,
                         cudaFuncAttributeMaxDynamicSharedMemorySize, SMEM_BYTES);
    cudaFuncSetAttribute(sage_fused_kernel<false>,
                         cudaFuncAttributeMaxDynamicSharedMemorySize, SMEM_BYTES);

    const int eb4 = (E / 4 + 255) / 256 + 1;
    const int scanb = (M + SCAN_BLK - 1) / SCAN_BLK;
    const int gemmb = (M + 63) / 64;
    const size_t plane = (size_t)128 * 128;

    // Setup: weights (+zero deg) -> count -> scan(2) -> fill
    convert_w_zero_kernel<<<256, 128>>>(W0l, W0r, W1l, W1r, M);
    count_deg_kernel<<<eb4, 256>>>(dst, E);
    scan_part_kernel<<<scanb, SCAN_BLK>>>(M);
    scan_write_kernel<<<scanb, SCAN_BLK>>>(M);
    fill_csr_kernel<<<eb4, 256>>>(src, dst, E);

    // Layer 0: fused gather + GEMM (+ReLU)
    sage_fused_kernel<true><<<gemmb, 256, SMEM_BYTES>>>(
        x, bp_ptr, bp_ptr + plane, b0l, h_ptr, M);

    // Layer 1: fused gather + GEMM
    sage_fused_kernel<false><<<gemmb, 256, SMEM_BYTES>>>(
        h_ptr, bp_ptr + 2 * plane, bp_ptr + 3 * plane, b1l, out, M);
}

// round 14
// speedup vs baseline: 1.2716x; 1.1356x over previous
#include <cuda_runtime.h>
#include <cuda_fp16.h>
#include <cstddef>
#include <cstdint>

#define D 128
#define MAX_NODES 50000
#define MAX_EDGES 800000

typedef unsigned int u32;

// Static device scratch (no allocations allowed).
__device__ float g_h[(size_t)MAX_NODES * D];     // layer-0 output
__device__ int   g_degi[MAX_NODES];
__device__ int   g_off[MAX_NODES];
__device__ int   g_cur[MAX_NODES];
__device__ int   g_ssrc[MAX_EDGES];
__device__ int   g_part[64];
// Pre-packed fp16 weights: [layer][kp][n], u32 = half2(k=2kp, k=2kp+1).
__device__ u32 g_Bp[2][128][128];

// ---------------------------------------------------------------------------
// Weight conversion (single fp16 plane) + zero g_degi.
// grid = 256 (layer*128 + kp), block = 128 (n).
// ---------------------------------------------------------------------------
__global__ void convert_w_zero_kernel(const float* __restrict__ W0l,
                                      const float* __restrict__ W0r,
                                      const float* __restrict__ W1l,
                                      const float* __restrict__ W1r,
                                      int M) {
    int kp = blockIdx.x & 127;
    int layer = blockIdx.x >> 7;
    int n = threadIdx.x;
    int k0 = 2 * kp;
    const float* W = layer ? (k0 < D ? W1l : W1r) : (k0 < D ? W0l : W0r);
    float v0 = W[(size_t)(k0 & (D - 1)) * D + n];
    float v1 = W[(size_t)((k0 + 1) & (D - 1)) * D + n];
    __half2 h2 = __floats2half2_rn(v0, v1);
    g_Bp[layer][kp][n] = *reinterpret_cast<u32*>(&h2);

    int idx = blockIdx.x * 128 + n;          // 32768 threads, 2 strides cover 50k
    if (idx < M) g_degi[idx] = 0;
    idx += 32768;
    if (idx < M) g_degi[idx] = 0;
}

__global__ void count_deg_kernel(const int* __restrict__ dst, int E) {
    int i = (blockIdx.x * blockDim.x + threadIdx.x) * 4;
    if (i + 4 <= E) {
        int4 d = *reinterpret_cast<const int4*>(dst + i);
        atomicAdd(&g_degi[d.x], 1);
        atomicAdd(&g_degi[d.y], 1);
        atomicAdd(&g_degi[d.z], 1);
        atomicAdd(&g_degi[d.w], 1);
    } else {
        for (; i < E; ++i) atomicAdd(&g_degi[dst[i]], 1);
    }
}

#define SCAN_BLK 1024
__global__ void scan_part_kernel(int n) {
    __shared__ int red[SCAN_BLK];
    int tid = threadIdx.x;
    int i = blockIdx.x * SCAN_BLK + tid;
    red[tid] = (i < n) ? g_degi[i] : 0;
    __syncthreads();
#pragma unroll
    for (int ofs = SCAN_BLK / 2; ofs > 0; ofs >>= 1) {
        if (tid < ofs) red[tid] += red[tid + ofs];
        __syncthreads();
    }
    if (tid == 0) g_part[blockIdx.x] = red[0];
}

// Block scan + serial base accumulation (<=48 adds per block << launch latency).
__global__ void scan_write_kernel(int n) {
    __shared__ int s[SCAN_BLK];
    __shared__ int sbase;
    int tid = threadIdx.x;
    int i = blockIdx.x * SCAN_BLK + tid;
    int v = (i < n) ? g_degi[i] : 0;
    s[tid] = v;
    if (tid == 0) {
        int run = 0;
        for (int b = 0; b < blockIdx.x; ++b) run += g_part[b];
        sbase = run;
    }
    __syncthreads();
    for (int ofs = 1; ofs < SCAN_BLK; ofs <<= 1) {
        int t = (tid >= ofs) ? s[tid - ofs] : 0;
        __syncthreads();
        s[tid] += t;
        __syncthreads();
    }
    int excl = s[tid] - v + sbase;
    if (i < n) { g_off[i] = excl; g_cur[i] = excl; }
}

__global__ void fill_csr_kernel(const int* __restrict__ src,
                                const int* __restrict__ dst, int E) {
    int i = (blockIdx.x * blockDim.x + threadIdx.x) * 4;
    if (i + 4 <= E) {
        int4 d = *reinterpret_cast<const int4*>(dst + i);
        int4 s = *reinterpret_cast<const int4*>(src + i);
        int p0 = atomicAdd(&g_cur[d.x], 1);
        int p1 = atomicAdd(&g_cur[d.y], 1);
        int p2 = atomicAdd(&g_cur[d.z], 1);
        int p3 = atomicAdd(&g_cur[d.w], 1);
        g_ssrc[p0] = s.x;
        g_ssrc[p1] = s.y;
        g_ssrc[p2] = s.z;
        g_ssrc[p3] = s.w;
    } else {
        for (; i < E; ++i) g_ssrc[atomicAdd(&g_cur[dst[i]], 1)] = src[i];
    }
}

// ---------------------------------------------------------------------------
// Fused gather + SAGE GEMM (1x FP16 mma.sync.m16n8k16), BM=64 x BN=128 tiles.
//   A (agg / h rows) and B (weights) each rounded to a single fp16 plane:
//   combined quantization ~4e-4 rel (measured A-only: 2.8e-4), gate is 1e-3.
//   Phase 0: A = mean-gather of H over CSR neighbors (all warps gather).
//   Phase 1: A = H rows (skip path).
//   out = A0@Wl + A1@Wr + mask(deg>0).*bias (+ReLU).
// Smem 26.1KB/CTA; 4 CTAs/SM.
// ---------------------------------------------------------------------------
#define MMA_F16(c, a, b)                                                       \
    asm volatile(                                                              \
        "mma.sync.aligned.m16n8k16.row.col.f32.f16.f16.f32 "                   \
        "{%0,%1,%2,%3},{%4,%5,%6,%7},{%8,%9},{%0,%1,%2,%3};"                   \
        : "+f"((c)[0]), "+f"((c)[1]), "+f"((c)[2]), "+f"((c)[3])               \
        : "r"((a)[0]), "r"((a)[1]), "r"((a)[2]), "r"((a)[3]),                  \
          "r"((b)[0]), "r"((b)[1]))

#define AFS 68          // full-K A stride: 64 packed words + 4 pad
#define BS_STRIDE 136   // B chunk stride: 128 packed cols + 8 pad
#define SMEM_WORDS (64 * AFS + 16 * BS_STRIDE)
#define SMEM_BYTES (SMEM_WORDS * 4)

__device__ __forceinline__ u32 pack_h2(float x, float y) {
    __half2 h = __floats2half2_rn(x, y);
    return *reinterpret_cast<u32*>(&h);
}

template <bool RELU>
__global__ void __launch_bounds__(256, 4)
sage_fused_kernel(const float* __restrict__ H,
                  const u32* __restrict__ Bw,
                  const float* __restrict__ bias, float* __restrict__ out,
                  int M) {
    extern __shared__ u32 sm[];
    u32* As = sm;                                // 64 * AFS (single fp16 plane)
    u32* Bs = sm + 64 * AFS;                     // 16 * BS_STRIDE (single plane)

    const int tid = threadIdx.x;
    const int warp = tid >> 5;
    const int lane = tid & 31;
    const int gid = lane >> 2;
    const int tig = lane & 3;
    const int wm = (warp >> 2) * 32;
    const int wn = (warp & 3) * 32;
    const int block_row = blockIdx.x * 64;

    const int bkp = tid >> 4;            // B staging: packed-k row 0..15
    const int bcn = (tid & 15) * 8;      //           8 cols per thread

    // ---- gather phase: warp w produces A rows w*8 .. w*8+7 (mean of nbrs) ----
    for (int j = 0; j < 8; ++j) {
        int r = warp * 8 + j;
        int row = block_row + r;
        float4 a0 = make_float4(0.f, 0.f, 0.f, 0.f);
        float4 a1 = a0, a2 = a0, a3 = a0;
        if (row < M) {
            int beg = g_off[row];
            int dg = g_degi[row];
            int i = 0;
            for (; i + 4 <= dg; i += 4) {
                int s0 = g_ssrc[beg + i];
                int s1 = g_ssrc[beg + i + 1];
                int s2 = g_ssrc[beg + i + 2];
                int s3 = g_ssrc[beg + i + 3];
                float4 v0 = __ldg(reinterpret_cast<const float4*>(H + (size_t)s0 * D) + lane);
                float4 v1 = __ldg(reinterpret_cast<const float4*>(H + (size_t)s1 * D) + lane);
                float4 v2 = __ldg(reinterpret_cast<const float4*>(H + (size_t)s2 * D) + lane);
                float4 v3 = __ldg(reinterpret_cast<const float4*>(H + (size_t)s3 * D) + lane);
                a0.x += v0.x; a0.y += v0.y; a0.z += v0.z; a0.w += v0.w;
                a1.x += v1.x; a1.y += v1.y; a1.z += v1.z; a1.w += v1.w;
                a2.x += v2.x; a2.y += v2.y; a2.z += v2.z; a2.w += v2.w;
                a3.x += v3.x; a3.y += v3.y; a3.z += v3.z; a3.w += v3.w;
            }
            for (; i < dg; ++i) {
                int s = g_ssrc[beg + i];
                float4 v = __ldg(reinterpret_cast<const float4*>(H + (size_t)s * D) + lane);
                a0.x += v.x; a0.y += v.y; a0.z += v.z; a0.w += v.w;
            }
            float inv = (dg > 0) ? 1.0f / (float)dg : 0.0f;
            a0.x = (a0.x + a1.x + a2.x + a3.x) * inv;
            a0.y = (a0.y + a1.y + a2.y + a3.y) * inv;
            a0.z = (a0.z + a1.z + a2.z + a3.z) * inv;
            a0.w = (a0.w + a1.w + a2.w + a3.w) * inv;
        }
        int o = r * AFS + lane * 2;
        As[o] = pack_h2(a0.x, a0.y);
        As[o + 1] = pack_h2(a0.z, a0.w);
    }

    float acc[2][4][4];
#pragma unroll
    for (int i = 0; i < 2; ++i)
#pragma unroll
        for (int j = 0; j < 4; ++j)
#pragma unroll
            for (int r = 0; r < 4; ++r) acc[i][j][r] = 0.0f;

#pragma unroll 1
    for (int phase = 0; phase < 2; ++phase) {
        if (phase == 1) {
            __syncthreads();   // all phase-0 A-frag reads done before overwrite
            // restage A = H rows (skip path)
            for (int j = 0; j < 8; ++j) {
                int r = warp * 8 + j;
                int row = block_row + r;
                float4 v = make_float4(0.f, 0.f, 0.f, 0.f);
                if (row < M)
                    v = __ldg(reinterpret_cast<const float4*>(H + (size_t)row * D) + lane);
                int o = r * AFS + lane * 2;
                As[o] = pack_h2(v.x, v.y);
                As[o + 1] = pack_h2(v.z, v.w);
            }
        }
        const int kpbase = phase * 64;

#pragma unroll 1
        for (int k0 = 0; k0 < D; k0 += 32) {
            const int kc = k0 >> 1;   // packed-word base of this chunk (0,16,32,48)
            const u32* bsw = Bw + (size_t)(kpbase + kc + bkp) * 128 + bcn;
            uint4 b0 = __ldg(reinterpret_cast<const uint4*>(bsw));
            uint4 b1 = __ldg(reinterpret_cast<const uint4*>(bsw + 4));

            __syncthreads();   // previous chunk's Bs reads done; A stores visible
            {
                u32 o = bkp * BS_STRIDE + bcn;
                *reinterpret_cast<uint4*>(&Bs[o]) = b0;
                *reinterpret_cast<uint4*>(&Bs[o + 4]) = b1;
            }
            __syncthreads();

#pragma unroll
            for (int ks2 = 0; ks2 < 16; ks2 += 8) {
                u32 bf[4][2];
#pragma unroll
                for (int nt = 0; nt < 4; ++nt) {
                    int nc = wn + nt * 8 + gid;
                    bf[nt][0] = Bs[(ks2 + tig) * BS_STRIDE + nc];
                    bf[nt][1] = Bs[(ks2 + tig + 4) * BS_STRIDE + nc];
                }
#pragma unroll
                for (int mt = 0; mt < 2; ++mt) {
                    int rr0 = (wm + mt * 16 + gid) * AFS + kc;
                    int rr8 = rr0 + 8 * AFS;
                    u32 ah[4];
                    ah[0] = As[rr0 + ks2 + tig];
                    ah[1] = As[rr8 + ks2 + tig];
                    ah[2] = As[rr0 + ks2 + tig + 4];
                    ah[3] = As[rr8 + ks2 + tig + 4];
#pragma unroll
                    for (int nt = 0; nt < 4; ++nt) {
                        MMA_F16(acc[mt][nt], ah, bf[nt]);
                    }
                }
            }
        }
    }

    // Epilogue: + mask(deg>0)*bias, optional ReLU, float2 stores.
#pragma unroll
    for (int mt = 0; mt < 2; ++mt) {
#pragma unroll
        for (int nt = 0; nt < 4; ++nt) {
            int row0 = block_row + wm + mt * 16 + gid;
            int row1 = row0 + 8;
            int col = wn + nt * 8 + tig * 2;
            float b0v = bias[col];
            float b1v = bias[col + 1];
            if (row0 < M) {
                float m0 = (g_degi[row0] > 0) ? 1.0f : 0.0f;
                float x0 = acc[mt][nt][0] + m0 * b0v;
                float x1 = acc[mt][nt][1] + m0 * b1v;
                if (RELU) { x0 = fmaxf(x0, 0.0f); x1 = fmaxf(x1, 0.0f); }
                *reinterpret_cast<float2*>(out + (size_t)row0 * D + col) = make_float2(x0, x1);
            }
            if (row1 < M) {
                float m1 = (g_degi[row1] > 0) ? 1.0f : 0.0f;
                float x2 = acc[mt][nt][2] + m1 * b0v;
                float x3 = acc[mt][nt][3] + m1 * b1v;
                if (RELU) { x2 = fmaxf(x2, 0.0f); x3 = fmaxf(x3, 0.0f); }
                *reinterpret_cast<float2*>(out + (size_t)row1 * D + col) = make_float2(x2, x3);
            }
        }
    }
}

// ---------------------------------------------------------------------------
// Launch sequence (graph-capturable; all on default stream). 7 launches.
// ---------------------------------------------------------------------------
extern "C" void kernel_launch(void* const* d_in, const int* in_sizes, int n_in,
                              void* d_out, int out_size) {
    const float* x   = (const float*)d_in[0];
    const int*   ei  = (const int*)d_in[1];
    const float* W0l = (const float*)d_in[2];
    const float* b0l = (const float*)d_in[3];
    const float* W0r = (const float*)d_in[4];
    const float* W1l = (const float*)d_in[5];
    const float* b1l = (const float*)d_in[6];
    const float* W1r = (const float*)d_in[7];
    float* out = (float*)d_out;

    const int E = in_sizes[1] / 2;
    const int M = in_sizes[0] / D;
    const int* src = ei;
    const int* dst = ei + E;

    float* h_ptr = nullptr;
    u32* bp_ptr = nullptr;
    cudaGetSymbolAddress((void**)&h_ptr, g_h);
    cudaGetSymbolAddress((void**)&bp_ptr, g_Bp);

    cudaFuncSetAttribute(sage_fused_kernel<true>,
                         cudaFuncAttributeMaxDynamicSharedMemorySize, SMEM_BYTES);
    cudaFuncSetAttribute(sage_fused_kernel<false>,
                         cudaFuncAttributeMaxDynamicSharedMemorySize, SMEM_BYTES);

    const int eb4 = (E / 4 + 255) / 256 + 1;
    const int scanb = (M + SCAN_BLK - 1) / SCAN_BLK;
    const int gemmb = (M + 63) / 64;
    const size_t plane = (size_t)128 * 128;   // u32 per layer weight plane

    // Setup: weights (+zero deg) -> count -> scan(2) -> fill
    convert_w_zero_kernel<<<256, 128>>>(W0l, W0r, W1l, W1r, M);
    count_deg_kernel<<<eb4, 256>>>(dst, E);
    scan_part_kernel<<<scanb, SCAN_BLK>>>(M);
    scan_write_kernel<<<scanb, SCAN_BLK>>>(M);
    fill_csr_kernel<<<eb4, 256>>>(src, dst, E);

    // Layer 0: fused gather + GEMM (+ReLU)
    sage_fused_kernel<true><<<gemmb, 256, SMEM_BYTES>>>(
        x, bp_ptr, b0l, h_ptr, M);

    // Layer 1: fused gather + GEMM
    sage_fused_kernel<false><<<gemmb, 256, SMEM_BYTES>>>(
        h_ptr, bp_ptr + plane, b1l, out, M);
}

// round 15
// speedup vs baseline: 1.3250x; 1.0420x over previous
#include <cuda_runtime.h>
#include <cuda_fp16.h>
#include <cstddef>
#include <cstdint>

#define D 128
#define DW 64            // packed half2 words per row
#define MAX_NODES 50000
#define MAX_EDGES 800000

typedef unsigned int u32;

// Static device scratch (no allocations allowed).
__device__ u32   g_xh[(size_t)MAX_NODES * DW];   // x as packed half2 (12.8 MB)
__device__ u32   g_h[(size_t)MAX_NODES * DW];    // layer-0 output, packed half2
__device__ int   g_degi[MAX_NODES];
__device__ int   g_off[MAX_NODES];
__device__ int   g_cur[MAX_NODES];
__device__ int   g_ssrc[MAX_EDGES];
__device__ int   g_part[64];
// Pre-packed fp16 weights: [layer][kp][n], u32 = half2(k=2kp, k=2kp+1).
__device__ u32 g_Bp[2][128][128];

__device__ __forceinline__ u32 pack_h2(float x, float y) {
    __half2 h = __floats2half2_rn(x, y);
    return *reinterpret_cast<u32*>(&h);
}

// ---------------------------------------------------------------------------
// Weight conversion (single fp16 plane) + zero g_degi.
// grid = 256 (layer*128 + kp), block = 128 (n).
// ---------------------------------------------------------------------------
__global__ void convert_w_zero_kernel(const float* __restrict__ W0l,
                                      const float* __restrict__ W0r,
                                      const float* __restrict__ W1l,
                                      const float* __restrict__ W1r,
                                      int M) {
    int kp = blockIdx.x & 127;
    int layer = blockIdx.x >> 7;
    int n = threadIdx.x;
    int k0 = 2 * kp;
    const float* W = layer ? (k0 < D ? W1l : W1r) : (k0 < D ? W0l : W0r);
    float v0 = W[(size_t)(k0 & (D - 1)) * D + n];
    float v1 = W[(size_t)((k0 + 1) & (D - 1)) * D + n];
    g_Bp[layer][kp][n] = pack_h2(v0, v1);

    int idx = blockIdx.x * 128 + n;          // 32768 threads, 2 strides cover 50k
    if (idx < M) g_degi[idx] = 0;
    idx += 32768;
    if (idx < M) g_degi[idx] = 0;
}

// x -> packed half2 (one quantization; pre-aggregation error analyzed in header).
__global__ void convert_x_kernel(const float* __restrict__ x, int nwords) {
    int i = blockIdx.x * blockDim.x + threadIdx.x;
    if (i < nwords) {
        float2 v = *reinterpret_cast<const float2*>(x + 2 * (size_t)i);
        g_xh[i] = pack_h2(v.x, v.y);
    }
}

__global__ void count_deg_kernel(const int* __restrict__ dst, int E) {
    int i = (blockIdx.x * blockDim.x + threadIdx.x) * 4;
    if (i + 4 <= E) {
        int4 d = *reinterpret_cast<const int4*>(dst + i);
        atomicAdd(&g_degi[d.x], 1);
        atomicAdd(&g_degi[d.y], 1);
        atomicAdd(&g_degi[d.z], 1);
        atomicAdd(&g_degi[d.w], 1);
    } else {
        for (; i < E; ++i) atomicAdd(&g_degi[dst[i]], 1);
    }
}

#define SCAN_BLK 1024
__global__ void scan_part_kernel(int n) {
    __shared__ int red[SCAN_BLK];
    int tid = threadIdx.x;
    int i = blockIdx.x * SCAN_BLK + tid;
    red[tid] = (i < n) ? g_degi[i] : 0;
    __syncthreads();
#pragma unroll
    for (int ofs = SCAN_BLK / 2; ofs > 0; ofs >>= 1) {
        if (tid < ofs) red[tid] += red[tid + ofs];
        __syncthreads();
    }
    if (tid == 0) g_part[blockIdx.x] = red[0];
}

// Block scan + serial base accumulation (<=48 adds per block << launch latency).
__global__ void scan_write_kernel(int n) {
    __shared__ int s[SCAN_BLK];
    __shared__ int sbase;
    int tid = threadIdx.x;
    int i = blockIdx.x * SCAN_BLK + tid;
    int v = (i < n) ? g_degi[i] : 0;
    s[tid] = v;
    if (tid == 0) {
        int run = 0;
        for (int b = 0; b < blockIdx.x; ++b) run += g_part[b];
        sbase = run;
    }
    __syncthreads();
    for (int ofs = 1; ofs < SCAN_BLK; ofs <<= 1) {
        int t = (tid >= ofs) ? s[tid - ofs] : 0;
        __syncthreads();
        s[tid] += t;
        __syncthreads();
    }
    int excl = s[tid] - v + sbase;
    if (i < n) { g_off[i] = excl; g_cur[i] = excl; }
}

__global__ void fill_csr_kernel(const int* __restrict__ src,
                                const int* __restrict__ dst, int E) {
    int i = (blockIdx.x * blockDim.x + threadIdx.x) * 4;
    if (i + 4 <= E) {
        int4 d = *reinterpret_cast<const int4*>(dst + i);
        int4 s = *reinterpret_cast<const int4*>(src + i);
        int p0 = atomicAdd(&g_cur[d.x], 1);
        int p1 = atomicAdd(&g_cur[d.y], 1);
        int p2 = atomicAdd(&g_cur[d.z], 1);
        int p3 = atomicAdd(&g_cur[d.w], 1);
        g_ssrc[p0] = s.x;
        g_ssrc[p1] = s.y;
        g_ssrc[p2] = s.z;
        g_ssrc[p3] = s.w;
    } else {
        for (; i < E; ++i) g_ssrc[atomicAdd(&g_cur[dst[i]], 1)] = src[i];
    }
}

// ---------------------------------------------------------------------------
// Fused gather + SAGE GEMM (1x FP16 mma.sync.m16n8k16), BM=64 x BN=128 tiles.
//   H is stored as packed half2 -> gather reads HALF the bytes (L2-BW bound).
//   Phase 0: A = mean-gather of H over CSR neighbors (fp32 accumulate).
//   Phase 1: A = H rows (exact copy, already fp16).
//   out = A0@Wl + A1@Wr + mask(deg>0).*bias (+ReLU).
//   HALF_OUT: write packed half2 (layer 0 -> g_h); else fp32 (final output).
// Smem 26.1KB/CTA; 4 CTAs/SM.
// ---------------------------------------------------------------------------
#define MMA_F16(c, a, b)                                                       \
    asm volatile(                                                              \
        "mma.sync.aligned.m16n8k16.row.col.f32.f16.f16.f32 "                   \
        "{%0,%1,%2,%3},{%4,%5,%6,%7},{%8,%9},{%0,%1,%2,%3};"                   \
        : "+f"((c)[0]), "+f"((c)[1]), "+f"((c)[2]), "+f"((c)[3])               \
        : "r"((a)[0]), "r"((a)[1]), "r"((a)[2]), "r"((a)[3]),                  \
          "r"((b)[0]), "r"((b)[1]))

#define AFS 68          // full-K A stride: 64 packed words + 4 pad
#define BS_STRIDE 136   // B chunk stride: 128 packed cols + 8 pad
#define SMEM_WORDS (64 * AFS + 16 * BS_STRIDE)
#define SMEM_BYTES (SMEM_WORDS * 4)

template <bool RELU, bool HALF_OUT>
__global__ void __launch_bounds__(256, 4)
sage_fused_kernel(const u32* __restrict__ Hh,     // packed half2 rows [M][64]
                  const u32* __restrict__ Bw,
                  const float* __restrict__ bias, void* __restrict__ outp,
                  int M) {
    extern __shared__ u32 sm[];
    u32* As = sm;                                // 64 * AFS (single fp16 plane)
    u32* Bs = sm + 64 * AFS;                     // 16 * BS_STRIDE (single plane)

    const int tid = threadIdx.x;
    const int warp = tid >> 5;
    const int lane = tid & 31;
    const int gid = lane >> 2;
    const int tig = lane & 3;
    const int wm = (warp >> 2) * 32;
    const int wn = (warp & 3) * 32;
    const int block_row = blockIdx.x * 64;

    const int bkp = tid >> 4;            // B staging: packed-k row 0..15
    const int bcn = (tid & 15) * 8;      //           8 cols per thread

    // ---- gather phase: warp w produces A rows w*8 .. w*8+7 (mean of nbrs) ----
    // Each lane covers 4 elems = 2 packed words = one uint2 (8B) per neighbor.
    for (int j = 0; j < 8; ++j) {
        int r = warp * 8 + j;
        int row = block_row + r;
        float4 a0 = make_float4(0.f, 0.f, 0.f, 0.f);
        float4 a1 = a0, a2 = a0, a3 = a0;
        if (row < M) {
            int beg = g_off[row];
            int dg = g_degi[row];
            int i = 0;
            for (; i + 4 <= dg; i += 4) {
                int s0 = g_ssrc[beg + i];
                int s1 = g_ssrc[beg + i + 1];
                int s2 = g_ssrc[beg + i + 2];
                int s3 = g_ssrc[beg + i + 3];
                uint2 w0 = __ldg(reinterpret_cast<const uint2*>(Hh + (size_t)s0 * DW) + lane);
                uint2 w1 = __ldg(reinterpret_cast<const uint2*>(Hh + (size_t)s1 * DW) + lane);
                uint2 w2 = __ldg(reinterpret_cast<const uint2*>(Hh + (size_t)s2 * DW) + lane);
                uint2 w3 = __ldg(reinterpret_cast<const uint2*>(Hh + (size_t)s3 * DW) + lane);
                float2 f;
                f = __half22float2(*reinterpret_cast<__half2*>(&w0.x)); a0.x += f.x; a0.y += f.y;
                f = __half22float2(*reinterpret_cast<__half2*>(&w0.y)); a0.z += f.x; a0.w += f.y;
                f = __half22float2(*reinterpret_cast<__half2*>(&w1.x)); a1.x += f.x; a1.y += f.y;
                f = __half22float2(*reinterpret_cast<__half2*>(&w1.y)); a1.z += f.x; a1.w += f.y;
                f = __half22float2(*reinterpret_cast<__half2*>(&w2.x)); a2.x += f.x; a2.y += f.y;
                f = __half22float2(*reinterpret_cast<__half2*>(&w2.y)); a2.z += f.x; a2.w += f.y;
                f = __half22float2(*reinterpret_cast<__half2*>(&w3.x)); a3.x += f.x; a3.y += f.y;
                f = __half22float2(*reinterpret_cast<__half2*>(&w3.y)); a3.z += f.x; a3.w += f.y;
            }
            for (; i < dg; ++i) {
                int s = g_ssrc[beg + i];
                uint2 w = __ldg(reinterpret_cast<const uint2*>(Hh + (size_t)s * DW) + lane);
                float2 f;
                f = __half22float2(*reinterpret_cast<__half2*>(&w.x)); a0.x += f.x; a0.y += f.y;
                f = __half22float2(*reinterpret_cast<__half2*>(&w.y)); a0.z += f.x; a0.w += f.y;
            }
            float inv = (dg > 0) ? 1.0f / (float)dg : 0.0f;
            a0.x = (a0.x + a1.x + a2.x + a3.x) * inv;
            a0.y = (a0.y + a1.y + a2.y + a3.y) * inv;
            a0.z = (a0.z + a1.z + a2.z + a3.z) * inv;
            a0.w = (a0.w + a1.w + a2.w + a3.w) * inv;
        }
        int o = r * AFS + lane * 2;
        As[o] = pack_h2(a0.x, a0.y);
        As[o + 1] = pack_h2(a0.z, a0.w);
    }

    float acc[2][4][4];
#pragma unroll
    for (int i = 0; i < 2; ++i)
#pragma unroll
        for (int j = 0; j < 4; ++j)
#pragma unroll
            for (int r = 0; r < 4; ++r) acc[i][j][r] = 0.0f;

#pragma unroll 1
    for (int phase = 0; phase < 2; ++phase) {
        if (phase == 1) {
            __syncthreads();   // all phase-0 A-frag reads done before overwrite
            // restage A = H rows (skip path; exact copy, already fp16)
            for (int j = 0; j < 8; ++j) {
                int r = warp * 8 + j;
                int row = block_row + r;
                uint2 w = make_uint2(0u, 0u);
                if (row < M)
                    w = __ldg(reinterpret_cast<const uint2*>(Hh + (size_t)row * DW) + lane);
                int o = r * AFS + lane * 2;
                As[o] = w.x;
                As[o + 1] = w.y;
            }
        }
        const int kpbase = phase * 64;

#pragma unroll 1
        for (int k0 = 0; k0 < D; k0 += 32) {
            const int kc = k0 >> 1;   // packed-word base of this chunk (0,16,32,48)
            const u32* bsw = Bw + (size_t)(kpbase + kc + bkp) * 128 + bcn;
            uint4 b0 = __ldg(reinterpret_cast<const uint4*>(bsw));
            uint4 b1 = __ldg(reinterpret_cast<const uint4*>(bsw + 4));

            __syncthreads();   // previous chunk's Bs reads done; A stores visible
            {
                u32 o = bkp * BS_STRIDE + bcn;
                *reinterpret_cast<uint4*>(&Bs[o]) = b0;
                *reinterpret_cast<uint4*>(&Bs[o + 4]) = b1;
            }
            __syncthreads();

#pragma unroll
            for (int ks2 = 0; ks2 < 16; ks2 += 8) {
                u32 bf[4][2];
#pragma unroll
                for (int nt = 0; nt < 4; ++nt) {
                    int nc = wn + nt * 8 + gid;
                    bf[nt][0] = Bs[(ks2 + tig) * BS_STRIDE + nc];
                    bf[nt][1] = Bs[(ks2 + tig + 4) * BS_STRIDE + nc];
                }
#pragma unroll
                for (int mt = 0; mt < 2; ++mt) {
                    int rr0 = (wm + mt * 16 + gid) * AFS + kc;
                    int rr8 = rr0 + 8 * AFS;
                    u32 ah[4];
                    ah[0] = As[rr0 + ks2 + tig];
                    ah[1] = As[rr8 + ks2 + tig];
                    ah[2] = As[rr0 + ks2 + tig + 4];
                    ah[3] = As[rr8 + ks2 + tig + 4];
#pragma unroll
                    for (int nt = 0; nt < 4; ++nt) {
                        MMA_F16(acc[mt][nt], ah, bf[nt]);
                    }
                }
            }
        }
    }

    // Epilogue: + mask(deg>0)*bias, optional ReLU; half2 or fp32 stores.
#pragma unroll
    for (int mt = 0; mt < 2; ++mt) {
#pragma unroll
        for (int nt = 0; nt < 4; ++nt) {
            int row0 = block_row + wm + mt * 16 + gid;
            int row1 = row0 + 8;
            int col = wn + nt * 8 + tig * 2;   // always even
            float b0v = bias[col];
            float b1v = bias[col + 1];
            if (row0 < M) {
                float m0 = (g_degi[row0] > 0) ? 1.0f : 0.0f;
                float x0 = acc[mt][nt][0] + m0 * b0v;
                float x1 = acc[mt][nt][1] + m0 * b1v;
                if (RELU) { x0 = fmaxf(x0, 0.0f); x1 = fmaxf(x1, 0.0f); }
                if (HALF_OUT)
                    ((u32*)outp)[(size_t)row0 * DW + (col >> 1)] = pack_h2(x0, x1);
                else
                    *reinterpret_cast<float2*>((float*)outp + (size_t)row0 * D + col) =
                        make_float2(x0, x1);
            }
            if (row1 < M) {
                float m1 = (g_degi[row1] > 0) ? 1.0f : 0.0f;
                float x2 = acc[mt][nt][2] + m1 * b0v;
                float x3 = acc[mt][nt][3] + m1 * b1v;
                if (RELU) { x2 = fmaxf(x2, 0.0f); x3 = fmaxf(x3, 0.0f); }
                if (HALF_OUT)
                    ((u32*)outp)[(size_t)row1 * DW + (col >> 1)] = pack_h2(x2, x3);
                else
                    *reinterpret_cast<float2*>((float*)outp + (size_t)row1 * D + col) =
                        make_float2(x2, x3);
            }
        }
    }
}

// ---------------------------------------------------------------------------
// Launch sequence (graph-capturable; all on default stream). 8 launches.
// ---------------------------------------------------------------------------
extern "C" void kernel_launch(void* const* d_in, const int* in_sizes, int n_in,
                              void* d_out, int out_size) {
    const float* x   = (const float*)d_in[0];
    const int*   ei  = (const int*)d_in[1];
    const float* W0l = (const float*)d_in[2];
    const float* b0l = (const float*)d_in[3];
    const float* W0r = (const float*)d_in[4];
    const float* W1l = (const float*)d_in[5];
    const float* b1l = (const float*)d_in[6];
    const float* W1r = (const float*)d_in[7];
    float* out = (float*)d_out;

    const int E = in_sizes[1] / 2;
    const int M = in_sizes[0] / D;
    const int* src = ei;
    const int* dst = ei + E;

    u32* xh_ptr = nullptr;
    u32* h_ptr = nullptr;
    u32* bp_ptr = nullptr;
    cudaGetSymbolAddress((void**)&xh_ptr, g_xh);
    cudaGetSymbolAddress((void**)&h_ptr, g_h);
    cudaGetSymbolAddress((void**)&bp_ptr, g_Bp);

    cudaFuncSetAttribute((const void*)sage_fused_kernel<true, true>,
                         cudaFuncAttributeMaxDynamicSharedMemorySize, SMEM_BYTES);
    cudaFuncSetAttribute((const void*)sage_fused_kernel<false, false>,
                         cudaFuncAttributeMaxDynamicSharedMemorySize, SMEM_BYTES);

    const int eb4 = (E / 4 + 255) / 256 + 1;
    const int scanb = (M + SCAN_BLK - 1) / SCAN_BLK;
    const int gemmb = (M + 63) / 64;
    const int xwords = M * DW;
    const int xb = (xwords + 255) / 256;
    const size_t plane = (size_t)128 * 128;   // u32 per layer weight plane

    // Setup: weights (+zero deg) -> x fp16 -> count -> scan(2) -> fill
    convert_w_zero_kernel<<<256, 128>>>(W0l, W0r, W1l, W1r, M);
    convert_x_kernel<<<xb, 256>>>(x, xwords);
    count_deg_kernel<<<eb4, 256>>>(dst, E);
    scan_part_kernel<<<scanb, SCAN_BLK>>>(M);
    scan_write_kernel<<<scanb, SCAN_BLK>>>(M);
    fill_csr_kernel<<<eb4, 256>>>(src, dst, E);

    // Layer 0: fused gather + GEMM (+ReLU), writes h as packed half2
    sage_fused_kernel<true, true><<<gemmb, 256, SMEM_BYTES>>>(
        xh_ptr, bp_ptr, b0l, (void*)h_ptr, M);

    // Layer 1: fused gather + GEMM, writes fp32 output
    sage_fused_kernel<false, false><<<gemmb, 256, SMEM_BYTES>>>(
        h_ptr, bp_ptr + plane, b1l, (void*)out, M);
}